// round 2
// baseline (speedup 1.0000x reference)
#include <cuda_runtime.h>

// Problem constants (fixed by the reference).
#define B_SZ   32
#define N_IN   1024
#define N_OUT  1024
#define NCHUNK 32                 // i-dimension split -> grid.x (1024 CTAs total)
#define CHUNK  (N_IN / NCHUNK)    // 32 i-rows per block
#define THREADS 256               // each thread: 4 contiguous o-columns (float4)

__global__ void zero_out_kernel(float* __restrict__ out, int n) {
    int idx = blockIdx.x * blockDim.x + threadIdx.x;
    if (idx < n) out[idx] = 0.0f;
}

__global__ __launch_bounds__(THREADS)
void synapses_kernel(const float* __restrict__ in_spikes,  // [B, N_IN]
                     const float* __restrict__ mem,        // [B, N_OUT]
                     const float* __restrict__ rev,        // [B, N_IN]
                     const float* __restrict__ syn,        // [B, N_IN, N_OUT]
                     const float* __restrict__ weights,    // [N_IN, N_OUT]
                     float* __restrict__ out)              // [B, N_OUT]
{
    __shared__ float s_sp[CHUNK];
    __shared__ float s_rv[CHUNK];

    const int b  = blockIdx.y;
    const int i0 = blockIdx.x * CHUNK;
    const int t  = threadIdx.x;

    // Stage the per-i scalars for this chunk once.
    if (t < CHUNK) {
        s_sp[t] = in_spikes[b * N_IN + i0 + t];
        s_rv[t] = rev[b * N_IN + i0 + t];
    }
    __syncthreads();

    const float decay = 1.0f - 1.0f / 5.0f;  // TAU = 5

    // float4 views; o is the contiguous dimension.
    const float4* __restrict__ syn4 =
        (const float4*)(syn + ((size_t)b * N_IN + i0) * N_OUT);
    const float4* __restrict__ w4 =
        (const float4*)(weights + (size_t)i0 * N_OUT);

    float4 ar = make_float4(0.f, 0.f, 0.f, 0.f);  // Σ cond*rev
    float4 as = make_float4(0.f, 0.f, 0.f, 0.f);  // Σ cond

    #pragma unroll 4
    for (int i = 0; i < CHUNK; ++i) {
        const float sp = s_sp[i];
        const float rv = s_rv[i];
        const float4 s = syn4[i * (N_OUT / 4) + t];
        const float4 w = w4[i * (N_OUT / 4) + t];

        // cond = (syn*decay + sp) * W
        float c0 = fmaf(s.x, decay, sp) * w.x;
        float c1 = fmaf(s.y, decay, sp) * w.y;
        float c2 = fmaf(s.z, decay, sp) * w.z;
        float c3 = fmaf(s.w, decay, sp) * w.w;

        ar.x = fmaf(c0, rv, ar.x);  as.x += c0;
        ar.y = fmaf(c1, rv, ar.y);  as.y += c1;
        ar.z = fmaf(c2, rv, ar.z);  as.z += c2;
        ar.w = fmaf(c3, rv, ar.w);  as.w += c3;
    }

    // Partial contribution of this i-chunk: acc_rev - mem * acc_sum
    // (linear in the partition, so partials sum to the full result).
    const int o = t * 4;
    const float4 m = *(const float4*)(mem + (size_t)b * N_OUT + o);

    float* dst = out + (size_t)b * N_OUT + o;
    atomicAdd(dst + 0, fmaf(-m.x, as.x, ar.x));
    atomicAdd(dst + 1, fmaf(-m.y, as.y, ar.y));
    atomicAdd(dst + 2, fmaf(-m.z, as.z, ar.z));
    atomicAdd(dst + 3, fmaf(-m.w, as.w, ar.w));
}

extern "C" void kernel_launch(void* const* d_in, const int* in_sizes, int n_in,
                              void* d_out, int out_size) {
    const float* in_spikes = (const float*)d_in[0];
    const float* mem       = (const float*)d_in[1];
    const float* rev       = (const float*)d_in[2];
    const float* syn       = (const float*)d_in[3];
    const float* weights   = (const float*)d_in[4];
    float* out = (float*)d_out;

    // d_out is poisoned; the main kernel accumulates via atomicAdd.
    zero_out_kernel<<<(B_SZ * N_OUT + 255) / 256, 256>>>(out, B_SZ * N_OUT);

    dim3 grid(NCHUNK, B_SZ);
    synapses_kernel<<<grid, THREADS>>>(in_spikes, mem, rev, syn, weights, out);
}

// round 4
// speedup vs baseline: 1.3750x; 1.3750x over previous
#include <cuda_runtime.h>

// Problem constants (fixed by the reference).
#define B_SZ   32
#define N_IN   1024
#define N_OUT  1024
#define NCHUNK 16                 // i-dimension split -> grid.x (512 CTAs total)
#define CHUNK  (N_IN / NCHUNK)    // 64 i-rows per block
#define THREADS 256               // each thread: 4 contiguous o-columns (float4)

__global__ void zero_out_kernel(float* __restrict__ out, int n) {
    int idx = blockIdx.x * blockDim.x + threadIdx.x;
    if (idx < n) out[idx] = 0.0f;
}

__global__ __launch_bounds__(THREADS)
void synapses_kernel(const float* __restrict__ in_spikes,  // [B, N_IN]
                     const float* __restrict__ mem,        // [B, N_OUT]
                     const float* __restrict__ rev,        // [B, N_IN]
                     const float* __restrict__ syn,        // [B, N_IN, N_OUT]
                     const float* __restrict__ weights,    // [N_IN, N_OUT]
                     float* __restrict__ out)              // [B, N_OUT]
{
    __shared__ float s_sp[CHUNK];
    __shared__ float s_rv[CHUNK];

    const int b  = blockIdx.y;
    const int i0 = blockIdx.x * CHUNK;
    const int t  = threadIdx.x;

    if (t < CHUNK) {
        s_sp[t] = in_spikes[b * N_IN + i0 + t];
        s_rv[t] = rev[b * N_IN + i0 + t];
    }
    __syncthreads();

    const float decay = 1.0f - 1.0f / 5.0f;  // TAU = 5

    const float4* __restrict__ syn4 =
        (const float4*)(syn + ((size_t)b * N_IN + i0) * N_OUT);
    const float4* __restrict__ w4 =
        (const float4*)(weights + (size_t)i0 * N_OUT);
    const int STRIDE = N_OUT / 4;  // 256 float4 per i-row

    float4 ar = make_float4(0.f, 0.f, 0.f, 0.f);  // Σ cond*rev
    float4 as = make_float4(0.f, 0.f, 0.f, 0.f);  // Σ cond

    // Manual 4-row unroll, ALL 8 loads front-batched so ptxas keeps
    // MLP=8 in flight per thread (needs ~32 live load regs -> forces
    // register count well above 34 and hoists LDGs ahead of compute).
    for (int i = 0; i < CHUNK; i += 4) {
        const float4 s0 = __ldcs(syn4 + (i + 0) * STRIDE + t);  // streaming
        const float4 s1 = __ldcs(syn4 + (i + 1) * STRIDE + t);
        const float4 s2 = __ldcs(syn4 + (i + 2) * STRIDE + t);
        const float4 s3 = __ldcs(syn4 + (i + 3) * STRIDE + t);
        const float4 w0 = __ldg(w4 + (i + 0) * STRIDE + t);
        const float4 w1 = __ldg(w4 + (i + 1) * STRIDE + t);
        const float4 w2 = __ldg(w4 + (i + 2) * STRIDE + t);
        const float4 w3 = __ldg(w4 + (i + 3) * STRIDE + t);

        {
            const float sp = s_sp[i + 0], rv = s_rv[i + 0];
            float c0 = fmaf(s0.x, decay, sp) * w0.x;
            float c1 = fmaf(s0.y, decay, sp) * w0.y;
            float c2 = fmaf(s0.z, decay, sp) * w0.z;
            float c3 = fmaf(s0.w, decay, sp) * w0.w;
            ar.x = fmaf(c0, rv, ar.x);  as.x += c0;
            ar.y = fmaf(c1, rv, ar.y);  as.y += c1;
            ar.z = fmaf(c2, rv, ar.z);  as.z += c2;
            ar.w = fmaf(c3, rv, ar.w);  as.w += c3;
        }
        {
            const float sp = s_sp[i + 1], rv = s_rv[i + 1];
            float c0 = fmaf(s1.x, decay, sp) * w1.x;
            float c1 = fmaf(s1.y, decay, sp) * w1.y;
            float c2 = fmaf(s1.z, decay, sp) * w1.z;
            float c3 = fmaf(s1.w, decay, sp) * w1.w;
            ar.x = fmaf(c0, rv, ar.x);  as.x += c0;
            ar.y = fmaf(c1, rv, ar.y);  as.y += c1;
            ar.z = fmaf(c2, rv, ar.z);  as.z += c2;
            ar.w = fmaf(c3, rv, ar.w);  as.w += c3;
        }
        {
            const float sp = s_sp[i + 2], rv = s_rv[i + 2];
            float c0 = fmaf(s2.x, decay, sp) * w2.x;
            float c1 = fmaf(s2.y, decay, sp) * w2.y;
            float c2 = fmaf(s2.z, decay, sp) * w2.z;
            float c3 = fmaf(s2.w, decay, sp) * w2.w;
            ar.x = fmaf(c0, rv, ar.x);  as.x += c0;
            ar.y = fmaf(c1, rv, ar.y);  as.y += c1;
            ar.z = fmaf(c2, rv, ar.z);  as.z += c2;
            ar.w = fmaf(c3, rv, ar.w);  as.w += c3;
        }
        {
            const float sp = s_sp[i + 3], rv = s_rv[i + 3];
            float c0 = fmaf(s3.x, decay, sp) * w3.x;
            float c1 = fmaf(s3.y, decay, sp) * w3.y;
            float c2 = fmaf(s3.z, decay, sp) * w3.z;
            float c3 = fmaf(s3.w, decay, sp) * w3.w;
            ar.x = fmaf(c0, rv, ar.x);  as.x += c0;
            ar.y = fmaf(c1, rv, ar.y);  as.y += c1;
            ar.z = fmaf(c2, rv, ar.z);  as.z += c2;
            ar.w = fmaf(c3, rv, ar.w);  as.w += c3;
        }
    }

    // Partial contribution of this i-chunk (linear in the i-partition).
    const int o = t * 4;
    const float4 m = *(const float4*)(mem + (size_t)b * N_OUT + o);

    float* dst = out + (size_t)b * N_OUT + o;
    atomicAdd(dst + 0, fmaf(-m.x, as.x, ar.x));
    atomicAdd(dst + 1, fmaf(-m.y, as.y, ar.y));
    atomicAdd(dst + 2, fmaf(-m.z, as.z, ar.z));
    atomicAdd(dst + 3, fmaf(-m.w, as.w, ar.w));
}

extern "C" void kernel_launch(void* const* d_in, const int* in_sizes, int n_in,
                              void* d_out, int out_size) {
    const float* in_spikes = (const float*)d_in[0];
    const float* mem       = (const float*)d_in[1];
    const float* rev       = (const float*)d_in[2];
    const float* syn       = (const float*)d_in[3];
    const float* weights   = (const float*)d_in[4];
    float* out = (float*)d_out;

    zero_out_kernel<<<(B_SZ * N_OUT + 255) / 256, 256>>>(out, B_SZ * N_OUT);

    dim3 grid(NCHUNK, B_SZ);
    synapses_kernel<<<grid, THREADS>>>(in_spikes, mem, rev, syn, weights, out);
}